// round 1
// baseline (speedup 1.0000x reference)
#include <cuda_runtime.h>
#include <stdint.h>

// Problem constants
#define IN_FLAT 1024
#define BATCH   512
#define NEURONS 4096
#define FOCUS   64

// Tiling
#define BCH   32          // batch rows per block (fits smem with pad-33 layout)
#define NPB   128         // neurons per block
#define TPB   512         // threads per block (16 warps)
#define NWARP (TPB/32)
#define NPW   (NPB/NWARP) // 8 neurons per warp
#define XSTR  33          // padded smem stride (conflict-free stage + gather)

// Pre-packed (offset, weight) pairs: off = idx * XSTR (word offset into x_sh)
__device__ uint4 g_pairs[NEURONS * (FOCUS/2)];

// ---------------------------------------------------------------------------
// Kernel 1: pack connections_index (+weights) into gather-ready uint4 pairs.
// Handles int64 OR int32 index dtype via a deterministic on-device sniff:
// int64 little-endian values in [0,1024) have all odd 4B words == 0.
// ---------------------------------------------------------------------------
__global__ void pack_pairs(const void* __restrict__ conn_raw,
                           const float* __restrict__ wgt) {
    int i = blockIdx.x * blockDim.x + threadIdx.x;
    if (i >= NEURONS * (FOCUS/2)) return;

    const int* ci32 = (const int*)conn_raw;
    // dtype sniff over first 32 candidate high-words (L1-cached broadcast)
    bool is64 = true;
    #pragma unroll
    for (int k = 1; k < 64; k += 2) is64 &= (ci32[k] == 0);

    int n = i >> 5;          // / (FOCUS/2)
    int j = i & 31;
    int base = n * FOCUS + 2 * j;

    int i0, i1;
    if (is64) {
        const long long* ci64 = (const long long*)conn_raw;
        i0 = (int)ci64[base];
        i1 = (int)ci64[base + 1];
    } else {
        i0 = ci32[base];
        i1 = ci32[base + 1];
    }

    uint4 p;
    p.x = (unsigned)(i0 * XSTR);
    p.y = __float_as_uint(wgt[base]);
    p.z = (unsigned)(i1 * XSTR);
    p.w = __float_as_uint(wgt[base + 1]);
    g_pairs[i] = p;
}

// ---------------------------------------------------------------------------
// Kernel 2: main gather-FMA kernel.
//   x_sh[col*33 + b_local] : staged x chunk (conflict-free both directions)
//   pr_sh                  : this block's pair table (broadcast LDS.128)
//   tr_sh                  : per-warp output transpose buffer (pad 9)
// ---------------------------------------------------------------------------
constexpr int X_SH_FLOATS  = IN_FLAT * XSTR;      // 33792 floats = 135168 B
constexpr int PR_SH_ELEMS  = NPB * (FOCUS/2);     // 4096 uint4   =  65536 B
constexpr int TR_SH_FLOATS = NWARP * BCH * 9;     // 4608 floats  =  18432 B
constexpr size_t SMEM_BYTES =
    (size_t)X_SH_FLOATS*4 + (size_t)PR_SH_ELEMS*16 + (size_t)TR_SH_FLOATS*4; // 219136

__global__ void __launch_bounds__(TPB, 1)
sparse_mm(const float* __restrict__ x, const float* __restrict__ bias,
          float* __restrict__ out) {
    extern __shared__ float sm[];
    float* x_sh  = sm;
    uint4* pr_sh = (uint4*)(sm + X_SH_FLOATS);
    float* tr_sh = (float*)(pr_sh + PR_SH_ELEMS);

    const int tid  = threadIdx.x;
    const int wid  = tid >> 5;
    const int lane = tid & 31;
    const int n0   = blockIdx.x * NPB;
    const int b0   = blockIdx.y * BCH;

    // ---- stage x[b0:b0+32, :] -> x_sh[c*33 + r]  (scalar: conflict-free STS)
    for (int r = wid; r < BCH; r += NWARP) {
        const float* row = x + (size_t)(b0 + r) * IN_FLAT;
        #pragma unroll
        for (int it = 0; it < IN_FLAT/32; ++it) {
            int c = it * 32 + lane;                 // consecutive lanes -> consecutive c
            x_sh[c * XSTR + r] = row[c];            // bank = (c + r) & 31: conflict-free
        }
    }

    // ---- stage this block's pair table (coalesced 16B copies)
    const uint4* pg = g_pairs + (size_t)n0 * (FOCUS/2);
    #pragma unroll
    for (int i = 0; i < PR_SH_ELEMS / TPB; ++i)     // 8 iterations exactly
        pr_sh[i * TPB + tid] = pg[i * TPB + tid];

    __syncthreads();

    // ---- main loop: warp = 8 neurons x 32 batch lanes
    const int nwb = wid * NPW;
    float* tr = tr_sh + wid * (BCH * 9);

    for (int nn = 0; nn < NPW; ++nn) {
        const uint4* pp = pr_sh + (nwb + nn) * (FOCUS/2);
        float a0 = 0.f, a1 = 0.f;
        #pragma unroll
        for (int j = 0; j < FOCUS/2; ++j) {
            uint4 p = pp[j];                                   // broadcast LDS.128 (2 focus)
            a0 = fmaf(x_sh[p.x + lane], __uint_as_float(p.y), a0);  // conflict-free gather
            a1 = fmaf(x_sh[p.z + lane], __uint_as_float(p.w), a1);
        }
        // stash per-lane result for warp-local transpose (bank-safe: 9 coprime 32)
        tr[lane * 9 + nn] = a0 + a1 + __ldg(bias + n0 + nwb + nn);
    }
    __syncwarp();

    // ---- de-scattered output: each STG.32 covers 4 x 32B contiguous sectors
    const int j  = lane & 7;       // neuron within warp group
    const int bq = lane >> 3;      // batch sub-row
    #pragma unroll
    for (int s = 0; s < 8; ++s) {
        int b = s * 4 + bq;
        out[(size_t)(b0 + b) * NEURONS + (n0 + nwb + j)] = tr[b * 9 + j];
    }
}

// ---------------------------------------------------------------------------
extern "C" void kernel_launch(void* const* d_in, const int* in_sizes, int n_in,
                              void* d_out, int out_size) {
    const float* x    = (const float*)d_in[0];
    const void*  conn = d_in[1];                  // int64 (or int32) indices
    const float* wgt  = (const float*)d_in[2];
    const float* bias = (const float*)d_in[3];
    float* out = (float*)d_out;

    cudaFuncSetAttribute(sparse_mm,
                         cudaFuncAttributeMaxDynamicSharedMemorySize,
                         (int)SMEM_BYTES);

    pack_pairs<<<(NEURONS * (FOCUS/2) + 255) / 256, 256>>>(conn, wgt);

    dim3 grid(NEURONS / NPB, BATCH / BCH);        // 32 x 16 = 512 blocks
    sparse_mm<<<grid, TPB, SMEM_BYTES>>>(x, bias, out);
}